// round 6
// baseline (speedup 1.0000x reference)
#include <cuda_runtime.h>
#include <cuda_bf16.h>
#include <math.h>

// Problem dims (fixed by the reference)
#define E     1024
#define H     2048
#define G     8192     // 4*H gate rows
#define TT    128      // title timesteps
#define TA    16       // author timesteps

// ---------------- device scratch (no allocation allowed) ----------------
__device__ float g_X_t[TT * E];      // gathered title embeddings
__device__ float g_X_a[TA * E];      // gathered author embeddings
__device__ float g_gx_t[TT * G];     // precomputed x-gates + bias (title)
__device__ float g_gx_a[TA * G];     // precomputed x-gates + bias (authors)
__device__ float g_h[2 * H];         // h ping-pong
__device__ float g_c[H];             // cell state
__device__ float g_hT[H];            // final title summary
__device__ float g_hA[H];            // final authors summary
__device__ float g_h1[H];
__device__ float g_h2[H];

// ---------------- embedding gather ----------------
// grid = TT + TA blocks, 256 threads; one row (1024 floats = 256 float4) per block
__global__ void gather_kernel(const int* __restrict__ xt, const int* __restrict__ xa,
                              const float* __restrict__ emb_t, const float* __restrict__ emb_a) {
    int row = blockIdx.x;
    const float4* src;
    float4* dst;
    if (row < TT) {
        src = (const float4*)(emb_t + (size_t)xt[row] * E);
        dst = (float4*)(g_X_t + (size_t)row * E);
    } else {
        int r = row - TT;
        src = (const float4*)(emb_a + (size_t)xa[r] * E);
        dst = (float4*)(g_X_a + (size_t)r * E);
    }
    dst[threadIdx.x] = src[threadIdx.x];
}

// ---------------- input-side GEMM:  C[T x G] = X[T x E] * W^T + (b_ih + b_hh) ----------------
// W is [G x E] row-major. Tiled: block covers 32 gate rows x up to 128 timesteps.
// grid = G/32 = 256 blocks, 256 threads. Each thread: 4x4 register tile.
#define GK 16
__global__ __launch_bounds__(256) void gemm_xW_kernel(int which,
                                                      const float* __restrict__ W,
                                                      const float* __restrict__ b_ih,
                                                      const float* __restrict__ b_hh,
                                                      int T) {
    const float* X = which ? g_X_a : g_X_t;
    float*       C = which ? g_gx_a : g_gx_t;

    __shared__ float Xs[128][GK + 1];
    __shared__ float Ws[32][GK + 1];

    const int tid = threadIdx.x;
    const int j0  = blockIdx.x * 32;
    const int tj  = (tid & 7) * 4;    // 0..28 (j within tile)
    const int tt  = (tid >> 3) * 4;   // 0..124 (t within tile)

    float acc[4][4];
#pragma unroll
    for (int a = 0; a < 4; a++)
#pragma unroll
        for (int b = 0; b < 4; b++) acc[a][b] = 0.f;

    for (int k0 = 0; k0 < E; k0 += GK) {
        for (int i = tid; i < T * GK; i += 256) {
            int t = i / GK, k = i - t * GK;
            Xs[t][k] = X[(size_t)t * E + k0 + k];
        }
        for (int i = tid; i < 32 * GK; i += 256) {
            int j = i / GK, k = i - j * GK;
            Ws[j][k] = W[(size_t)(j0 + j) * E + k0 + k];
        }
        __syncthreads();
#pragma unroll
        for (int k = 0; k < GK; k++) {
            float wv[4], xv[4];
#pragma unroll
            for (int a = 0; a < 4; a++) wv[a] = Ws[tj + a][k];
#pragma unroll
            for (int b = 0; b < 4; b++) xv[b] = Xs[tt + b][k];
#pragma unroll
            for (int a = 0; a < 4; a++)
#pragma unroll
                for (int b = 0; b < 4; b++) acc[a][b] = fmaf(wv[a], xv[b], acc[a][b]);
        }
        __syncthreads();
    }

#pragma unroll
    for (int a = 0; a < 4; a++) {
        int j = j0 + tj + a;
        float bias = b_ih[j] + b_hh[j];
#pragma unroll
        for (int b = 0; b < 4; b++) {
            int t = tt + b;
            if (t < T) C[(size_t)t * G + j] = acc[a][b] + bias;
        }
    }
}

// ---------------- zero h (buffer 0) and c ----------------
__global__ void init_state_kernel() {
    int i = blockIdx.x * blockDim.x + threadIdx.x;
    if (i < H) g_h[i] = 0.f;
    else if (i < 2 * H) g_c[i - H] = 0.f;
}

// ---------------- one LSTM step ----------------
// grid = H/4 = 512 blocks, 128 threads (4 warps).
// Block owns 4 hidden units; warp w computes gate w for all 4 units
// (rows w*H + u0..u0+3, contiguous). Then threads 0..3 do the pointwise update.
__global__ __launch_bounds__(128) void lstm_step_kernel(const float* __restrict__ W_hh,
                                                        int t, int which, int last) {
    __shared__ float sh[H];
    __shared__ float sg[16];  // [gate][unit]

    const float* gx   = (which ? g_gx_a : g_gx_t) + (size_t)t * G;
    const float* h_in = g_h + (size_t)(t & 1) * H;
    float* h_out = last ? (which ? g_hA : g_hT) : (g_h + (size_t)((t + 1) & 1) * H);

    const int tid = threadIdx.x;

    // load h into shared (2048 floats = 512 float4)
    float4* sh4 = (float4*)sh;
    const float4* h4 = (const float4*)h_in;
    for (int i = tid; i < H / 4; i += 128) sh4[i] = h4[i];
    __syncthreads();

    const int warp = tid >> 5, lane = tid & 31;
    const int u0 = blockIdx.x * 4;

#pragma unroll
    for (int r = 0; r < 4; r++) {
        int row = warp * H + u0 + r;
        const float4* w4 = (const float4*)(W_hh + (size_t)row * H);
        float s0 = 0.f, s1 = 0.f;
#pragma unroll
        for (int i = lane; i < H / 4; i += 64) {
            float4 w = w4[i], h = sh4[i];
            s0 = fmaf(w.x, h.x, fmaf(w.y, h.y, fmaf(w.z, h.z, fmaf(w.w, h.w, s0))));
            float4 w2 = w4[i + 32], h2 = sh4[i + 32];
            s1 = fmaf(w2.x, h2.x, fmaf(w2.y, h2.y, fmaf(w2.z, h2.z, fmaf(w2.w, h2.w, s1))));
        }
        float s = s0 + s1;
#pragma unroll
        for (int off = 16; off; off >>= 1) s += __shfl_xor_sync(0xFFFFFFFFu, s, off);
        if (lane == 0) sg[warp * 4 + r] = s + gx[row];
    }
    __syncthreads();

    if (tid < 4) {
        int u = u0 + tid;
        float gi = sg[0 * 4 + tid];
        float gf = sg[1 * 4 + tid];
        float gg = sg[2 * 4 + tid];
        float go = sg[3 * 4 + tid];
        float iv = 1.f / (1.f + expf(-gi));
        float fv = 1.f / (1.f + expf(-gf));
        float gv = tanhf(gg);
        float ov = 1.f / (1.f + expf(-go));
        float cn = fv * g_c[u] + iv * gv;
        g_c[u] = cn;
        h_out[u] = ov * tanhf(cn);
    }
}

// ---------------- MLP matvec layers ----------------
// layer 0: h1 = relu([hT;hA] @ W1^T + b1)   (K=4096, M=2048)
// layer 1: h2 = relu(h1 @ W2^T + b2)        (K=2048, M=2048)
// layer 2: out = h2 @ W3^T + b3             (K=2048, M=2)
// blockDim 128 (4 warps), warp-per-row.
__global__ __launch_bounds__(128) void mlp_kernel(const float* __restrict__ W,
                                                  const float* __restrict__ bias,
                                                  int layer, float* __restrict__ out_final) {
    __shared__ float sv[2 * H];

    const float* v1; const float* v2 = nullptr; float* out;
    int K, M; bool do_relu;
    if (layer == 0) { v1 = g_hT; v2 = g_hA; K = 2 * H; out = g_h1; M = H;  do_relu = true;  }
    else if (layer == 1) { v1 = g_h1; K = H; out = g_h2; M = H;  do_relu = true;  }
    else { v1 = g_h2; K = H; out = out_final; M = 2; do_relu = false; }

    float4* sv4 = (float4*)sv;
    for (int i = threadIdx.x; i < H / 4; i += 128) sv4[i] = ((const float4*)v1)[i];
    if (v2) for (int i = threadIdx.x; i < H / 4; i += 128) sv4[H / 4 + i] = ((const float4*)v2)[i];
    __syncthreads();

    const int warp = threadIdx.x >> 5, lane = threadIdx.x & 31;
    const int row = blockIdx.x * 4 + warp;
    if (row >= M) return;

    const float4* w4 = (const float4*)(W + (size_t)row * K);
    float s0 = 0.f, s1 = 0.f;
    const int nv = K / 4;
    for (int i = lane; i < nv; i += 64) {
        float4 w = w4[i], x = sv4[i];
        s0 = fmaf(w.x, x.x, fmaf(w.y, x.y, fmaf(w.z, x.z, fmaf(w.w, x.w, s0))));
        int i2 = i + 32;
        if (i2 < nv) {
            float4 w2 = w4[i2], x2 = sv4[i2];
            s1 = fmaf(w2.x, x2.x, fmaf(w2.y, x2.y, fmaf(w2.z, x2.z, fmaf(w2.w, x2.w, s1))));
        }
    }
    float s = s0 + s1;
#pragma unroll
    for (int off = 16; off; off >>= 1) s += __shfl_xor_sync(0xFFFFFFFFu, s, off);
    if (lane == 0) {
        float r = s + bias[row];
        out[row] = do_relu ? fmaxf(r, 0.f) : r;
    }
}

// ---------------- launcher ----------------
extern "C" void kernel_launch(void* const* d_in, const int* in_sizes, int n_in,
                              void* d_out, int out_size) {
    const int*   x_title   = (const int*)  d_in[0];
    const int*   x_authors = (const int*)  d_in[1];
    const float* emb_t     = (const float*)d_in[2];
    const float* emb_a     = (const float*)d_in[3];
    const float* W_ih_t    = (const float*)d_in[4];
    const float* W_hh_t    = (const float*)d_in[5];
    const float* b_ih_t    = (const float*)d_in[6];
    const float* b_hh_t    = (const float*)d_in[7];
    const float* W_ih_a    = (const float*)d_in[8];
    const float* W_hh_a    = (const float*)d_in[9];
    const float* b_ih_a    = (const float*)d_in[10];
    const float* b_hh_a    = (const float*)d_in[11];
    const float* W1        = (const float*)d_in[12];
    const float* b1        = (const float*)d_in[13];
    const float* W2        = (const float*)d_in[14];
    const float* b2        = (const float*)d_in[15];
    const float* W3        = (const float*)d_in[16];
    const float* b3        = (const float*)d_in[17];
    float* out = (float*)d_out;

    // 1. gather embeddings
    gather_kernel<<<TT + TA, 256>>>(x_title, x_authors, emb_t, emb_a);

    // 2. precompute input-side gates (+fused biases)
    gemm_xW_kernel<<<G / 32, 256>>>(0, W_ih_t, b_ih_t, b_hh_t, TT);
    gemm_xW_kernel<<<G / 32, 256>>>(1, W_ih_a, b_ih_a, b_hh_a, TA);

    // 3. title LSTM
    init_state_kernel<<<(2 * H + 255) / 256, 256>>>();
    for (int t = 0; t < TT; t++)
        lstm_step_kernel<<<H / 4, 128>>>(W_hh_t, t, 0, t == TT - 1);

    // 4. authors LSTM
    init_state_kernel<<<(2 * H + 255) / 256, 256>>>();
    for (int t = 0; t < TA; t++)
        lstm_step_kernel<<<H / 4, 128>>>(W_hh_a, t, 1, t == TA - 1);

    // 5. MLP head
    mlp_kernel<<<H / 4, 128>>>(W1, b1, 0, out);
    mlp_kernel<<<H / 4, 128>>>(W2, b2, 1, out);
    mlp_kernel<<<1, 128>>>(W3, b3, 2, out);
}

// round 7
// speedup vs baseline: 1.1562x; 1.1562x over previous
#include <cuda_runtime.h>
#include <cuda_bf16.h>
#include <math.h>

// Problem dims (fixed by the reference)
#define E     1024
#define H     2048
#define G     8192     // 4*H gate rows
#define TT    128      // title timesteps
#define TA    16       // author timesteps
#define WELEM ((size_t)G * H)   // 16,777,216 elements per W_hh

// ---------------- device scratch (no allocation allowed) ----------------
__device__ float g_X_t[TT * E];      // gathered title embeddings
__device__ float g_X_a[TA * E];      // gathered author embeddings
__device__ float g_gx_t[TT * G];     // precomputed x-gates + bias (title)
__device__ float g_gx_a[TA * G];     // precomputed x-gates + bias (authors)
__device__ __nv_bfloat16 g_Whh_bf[2 * WELEM];  // [0]=title, [1]=authors (64 MB)
__device__ float g_h_t[2 * H];       // title h ping-pong
__device__ float g_c_t[H];
__device__ float g_h_a[2 * H];       // author h ping-pong
__device__ float g_c_a[H];
__device__ float g_hT[H];            // final title summary
__device__ float g_hA[H];            // final authors summary
__device__ float g_h1[H];
__device__ float g_h2[H];

// ---------------- embedding gather ----------------
__global__ void gather_kernel(const int* __restrict__ xt, const int* __restrict__ xa,
                              const float* __restrict__ emb_t, const float* __restrict__ emb_a) {
    int row = blockIdx.x;
    const float4* src;
    float4* dst;
    if (row < TT) {
        src = (const float4*)(emb_t + (size_t)xt[row] * E);
        dst = (float4*)(g_X_t + (size_t)row * E);
    } else {
        int r = row - TT;
        src = (const float4*)(emb_a + (size_t)xa[r] * E);
        dst = (float4*)(g_X_a + (size_t)r * E);
    }
    dst[threadIdx.x] = src[threadIdx.x];
}

// ---------------- W_hh fp32 -> bf16 conversion (both matrices) ----------------
// One thread per bf16x2 pair. 2*8,388,608 pairs total.
__global__ __launch_bounds__(256) void convert_whh_kernel(const float* __restrict__ Wt,
                                                          const float* __restrict__ Wa) {
    size_t i = (size_t)blockIdx.x * blockDim.x + threadIdx.x;
    const size_t pairs = WELEM / 2;   // per matrix
    __nv_bfloat162* dst = (__nv_bfloat162*)g_Whh_bf;
    if (i < pairs) {
        float2 v = ((const float2*)Wt)[i];
        dst[i] = __float22bfloat162_rn(v);
    } else if (i < 2 * pairs) {
        float2 v = ((const float2*)Wa)[i - pairs];
        dst[i] = __float22bfloat162_rn(v);
    }
}

// ---------------- input-side GEMM:  C[T x G] = X[T x E] * W^T + (b_ih + b_hh) ----------------
#define GK 16
__global__ __launch_bounds__(256) void gemm_xW_kernel(int which,
                                                      const float* __restrict__ W,
                                                      const float* __restrict__ b_ih,
                                                      const float* __restrict__ b_hh,
                                                      int T) {
    const float* X = which ? g_X_a : g_X_t;
    float*       C = which ? g_gx_a : g_gx_t;

    __shared__ float Xs[128][GK + 1];
    __shared__ float Ws[32][GK + 1];

    const int tid = threadIdx.x;
    const int j0  = blockIdx.x * 32;
    const int tj  = (tid & 7) * 4;
    const int tt  = (tid >> 3) * 4;

    float acc[4][4];
#pragma unroll
    for (int a = 0; a < 4; a++)
#pragma unroll
        for (int b = 0; b < 4; b++) acc[a][b] = 0.f;

    for (int k0 = 0; k0 < E; k0 += GK) {
        for (int i = tid; i < T * GK; i += 256) {
            int t = i / GK, k = i - t * GK;
            Xs[t][k] = X[(size_t)t * E + k0 + k];
        }
        for (int i = tid; i < 32 * GK; i += 256) {
            int j = i / GK, k = i - j * GK;
            Ws[j][k] = W[(size_t)(j0 + j) * E + k0 + k];
        }
        __syncthreads();
#pragma unroll
        for (int k = 0; k < GK; k++) {
            float wv[4], xv[4];
#pragma unroll
            for (int a = 0; a < 4; a++) wv[a] = Ws[tj + a][k];
#pragma unroll
            for (int b = 0; b < 4; b++) xv[b] = Xs[tt + b][k];
#pragma unroll
            for (int a = 0; a < 4; a++)
#pragma unroll
                for (int b = 0; b < 4; b++) acc[a][b] = fmaf(wv[a], xv[b], acc[a][b]);
        }
        __syncthreads();
    }

#pragma unroll
    for (int a = 0; a < 4; a++) {
        int j = j0 + tj + a;
        float bias = b_ih[j] + b_hh[j];
#pragma unroll
        for (int b = 0; b < 4; b++) {
            int t = tt + b;
            if (t < T) C[(size_t)t * G + j] = acc[a][b] + bias;
        }
    }
}

// ---------------- zero initial state (both streams) ----------------
__global__ void init_state_kernel() {
    int i = blockIdx.x * blockDim.x + threadIdx.x;
    if (i < H)          g_h_t[i] = 0.f;
    else if (i < 2 * H) g_c_t[i - H] = 0.f;
    else if (i < 3 * H) g_h_a[i - 2 * H] = 0.f;
    else if (i < 4 * H) g_c_a[i - 3 * H] = 0.f;
}

// ---------------- one LSTM step (bf16 weights, fp32 accumulate) ----------------
// Title blocks: blockIdx 0..511. Author blocks (when grid=1024): 512..1023.
// Block owns 4 hidden units; warp w computes gate w's 4 rows.
__global__ __launch_bounds__(128) void lstm_step_kernel(int t, int lastT, int lastA) {
    __shared__ float sh[H];
    __shared__ float sg[16];

    const int stream = blockIdx.x >> 9;          // 0 = title, 1 = authors
    const int blk    = blockIdx.x & 511;

    const __nv_bfloat16* W = g_Whh_bf + (size_t)stream * WELEM;
    const float* gx   = (stream ? g_gx_a : g_gx_t) + (size_t)t * G;
    float* hbuf       = stream ? g_h_a : g_h_t;
    float* cbuf       = stream ? g_c_a : g_c_t;
    const int last    = stream ? (t == lastA) : (t == lastT);
    const float* h_in = hbuf + (size_t)(t & 1) * H;
    float* h_out      = last ? (stream ? g_hA : g_hT) : (hbuf + (size_t)((t + 1) & 1) * H);

    const int tid = threadIdx.x;

    float4* sh4 = (float4*)sh;
    const float4* h4 = (const float4*)h_in;
    for (int i = tid; i < H / 4; i += 128) sh4[i] = h4[i];
    __syncthreads();

    const int warp = tid >> 5, lane = tid & 31;
    const int u0 = blk * 4;

#pragma unroll
    for (int r = 0; r < 4; r++) {
        int row = warp * H + u0 + r;
        const uint4* w8 = (const uint4*)(W + (size_t)row * H);  // 8 bf16 per uint4, 256 per row
        float s = 0.f;
#pragma unroll
        for (int i = lane; i < 256; i += 32) {
            uint4 wv = w8[i];
            float4 h0 = sh4[2 * i], h1 = sh4[2 * i + 1];
            float2 a0 = __bfloat1622float2(*(const __nv_bfloat162*)&wv.x);
            float2 a1 = __bfloat1622float2(*(const __nv_bfloat162*)&wv.y);
            float2 a2 = __bfloat1622float2(*(const __nv_bfloat162*)&wv.z);
            float2 a3 = __bfloat1622float2(*(const __nv_bfloat162*)&wv.w);
            s = fmaf(a0.x, h0.x, s); s = fmaf(a0.y, h0.y, s);
            s = fmaf(a1.x, h0.z, s); s = fmaf(a1.y, h0.w, s);
            s = fmaf(a2.x, h1.x, s); s = fmaf(a2.y, h1.y, s);
            s = fmaf(a3.x, h1.z, s); s = fmaf(a3.y, h1.w, s);
        }
#pragma unroll
        for (int off = 16; off; off >>= 1) s += __shfl_xor_sync(0xFFFFFFFFu, s, off);
        if (lane == 0) sg[warp * 4 + r] = s + gx[row];
    }
    __syncthreads();

    if (tid < 4) {
        int u = u0 + tid;
        float gi = sg[0 * 4 + tid];
        float gf = sg[1 * 4 + tid];
        float gg = sg[2 * 4 + tid];
        float go = sg[3 * 4 + tid];
        float iv = 1.f / (1.f + expf(-gi));
        float fv = 1.f / (1.f + expf(-gf));
        float gv = tanhf(gg);
        float ov = 1.f / (1.f + expf(-go));
        float cn = fv * cbuf[u] + iv * gv;
        cbuf[u] = cn;
        h_out[u] = ov * tanhf(cn);
    }
}

// ---------------- MLP matvec layers ----------------
__global__ __launch_bounds__(128) void mlp_kernel(const float* __restrict__ W,
                                                  const float* __restrict__ bias,
                                                  int layer, float* __restrict__ out_final) {
    __shared__ float sv[2 * H];

    const float* v1; const float* v2 = nullptr; float* out;
    int K, M; bool do_relu;
    if (layer == 0) { v1 = g_hT; v2 = g_hA; K = 2 * H; out = g_h1; M = H;  do_relu = true;  }
    else if (layer == 1) { v1 = g_h1; K = H; out = g_h2; M = H;  do_relu = true;  }
    else { v1 = g_h2; K = H; out = out_final; M = 2; do_relu = false; }

    float4* sv4 = (float4*)sv;
    for (int i = threadIdx.x; i < H / 4; i += 128) sv4[i] = ((const float4*)v1)[i];
    if (v2) for (int i = threadIdx.x; i < H / 4; i += 128) sv4[H / 4 + i] = ((const float4*)v2)[i];
    __syncthreads();

    const int warp = threadIdx.x >> 5, lane = threadIdx.x & 31;
    const int row = blockIdx.x * 4 + warp;
    if (row >= M) return;

    const float4* w4 = (const float4*)(W + (size_t)row * K);
    float s0 = 0.f, s1 = 0.f;
    const int nv = K / 4;
    for (int i = lane; i < nv; i += 64) {
        float4 w = w4[i], x = sv4[i];
        s0 = fmaf(w.x, x.x, fmaf(w.y, x.y, fmaf(w.z, x.z, fmaf(w.w, x.w, s0))));
        int i2 = i + 32;
        if (i2 < nv) {
            float4 w2 = w4[i2], x2 = sv4[i2];
            s1 = fmaf(w2.x, x2.x, fmaf(w2.y, x2.y, fmaf(w2.z, x2.z, fmaf(w2.w, x2.w, s1))));
        }
    }
    float s = s0 + s1;
#pragma unroll
    for (int off = 16; off; off >>= 1) s += __shfl_xor_sync(0xFFFFFFFFu, s, off);
    if (lane == 0) {
        float r = s + bias[row];
        out[row] = do_relu ? fmaxf(r, 0.f) : r;
    }
}

// ---------------- launcher ----------------
extern "C" void kernel_launch(void* const* d_in, const int* in_sizes, int n_in,
                              void* d_out, int out_size) {
    const int*   x_title   = (const int*)  d_in[0];
    const int*   x_authors = (const int*)  d_in[1];
    const float* emb_t     = (const float*)d_in[2];
    const float* emb_a     = (const float*)d_in[3];
    const float* W_ih_t    = (const float*)d_in[4];
    const float* W_hh_t    = (const float*)d_in[5];
    const float* b_ih_t    = (const float*)d_in[6];
    const float* b_hh_t    = (const float*)d_in[7];
    const float* W_ih_a    = (const float*)d_in[8];
    const float* W_hh_a    = (const float*)d_in[9];
    const float* b_ih_a    = (const float*)d_in[10];
    const float* b_hh_a    = (const float*)d_in[11];
    const float* W1        = (const float*)d_in[12];
    const float* b1        = (const float*)d_in[13];
    const float* W2        = (const float*)d_in[14];
    const float* b2        = (const float*)d_in[15];
    const float* W3        = (const float*)d_in[16];
    const float* b3        = (const float*)d_in[17];
    float* out = (float*)d_out;

    // 1. gather embeddings + convert recurrent weights to bf16
    gather_kernel<<<TT + TA, 256>>>(x_title, x_authors, emb_t, emb_a);
    {
        size_t pairs = WELEM;  // 2 matrices * WELEM/2 pairs each
        int blocks = (int)((pairs + 255) / 256);
        convert_whh_kernel<<<blocks, 256>>>(W_hh_t, W_hh_a);
    }

    // 2. precompute input-side gates (+fused biases)
    gemm_xW_kernel<<<G / 32, 256>>>(0, W_ih_t, b_ih_t, b_hh_t, TT);
    gemm_xW_kernel<<<G / 32, 256>>>(1, W_ih_a, b_ih_a, b_hh_a, TA);

    // 3. both LSTMs; author steps (t<16) ride along in the same launch
    init_state_kernel<<<(4 * H + 255) / 256, 256>>>();
    for (int t = 0; t < TT; t++) {
        int grid = (t < TA) ? 1024 : 512;
        lstm_step_kernel<<<grid, 128>>>(t, TT - 1, TA - 1);
    }

    // 4. MLP head
    mlp_kernel<<<H / 4, 128>>>(W1, b1, 0, out);
    mlp_kernel<<<H / 4, 128>>>(W2, b2, 1, out);
    mlp_kernel<<<1, 128>>>(W3, b3, 2, out);
}